// round 2
// baseline (speedup 1.0000x reference)
#include <cuda_runtime.h>

#define NS 4096
#define NA 1024
#define ND 5
#define NH 64

typedef unsigned long long u64;

// ---- packed f32x2 helpers (sm_103a FFMA2 path, PTX-only per SASS_QUICKREF) ----
__device__ __forceinline__ u64 pack2(float lo, float hi) {
    u64 r; asm("mov.b64 %0, {%1, %2};" : "=l"(r) : "f"(lo), "f"(hi)); return r;
}
__device__ __forceinline__ u64 dup2(float x) {
    u64 r; asm("mov.b64 %0, {%1, %1};" : "=l"(r) : "f"(x)); return r;
}
__device__ __forceinline__ void unpack2(u64 v, float& lo, float& hi) {
    asm("mov.b64 {%0, %1}, %2;" : "=f"(lo), "=f"(hi) : "l"(v));
}
__device__ __forceinline__ u64 fma2(u64 a, u64 b, u64 c) {
    u64 d; asm("fma.rn.f32x2 %0, %1, %2, %3;" : "=l"(d) : "l"(a), "l"(b), "l"(c)); return d;
}

// tanh(x) = 1 - 2/(exp(2x)+1): 2 MUFU + ~4 fma-pipe ops, abs err ~1e-7.
__device__ __forceinline__ float fast_tanh(float x) {
    return 1.0f - __fdividef(2.0f, __expf(2.0f * x) + 1.0f);
}

__global__ void __launch_bounds__(256) mlp_grouped_kernel(
    const float* __restrict__ g,
    const float* __restrict__ W1, const float* __restrict__ b1,
    const float* __restrict__ W2, const float* __restrict__ b2,
    const float* __restrict__ W3, const float* __restrict__ b3,
    float* __restrict__ out)
{
    // Weights as f32x2 pairs over the output-neuron axis (row-major, adjacent j).
    __shared__ u64 sW1[ND * NH / 2];   // 160 pairs
    __shared__ u64 sW2[NH * NH / 2];   // 2048 pairs = 16 KB
    __shared__ u64 sW3[NH / 2];
    __shared__ u64 sB1[NH / 2];
    __shared__ u64 sB2[NH / 2];
    __shared__ float sB3;

    const int a   = blockIdx.x;
    const int tid = threadIdx.x;

    // ---- stage this atom's weights (contiguous 16B copies) ----
    {
        const ulonglong2* src = (const ulonglong2*)(W2 + (size_t)a * NH * NH);
        ulonglong2* dst = (ulonglong2*)sW2;
        #pragma unroll
        for (int i = 0; i < 4; i++) dst[tid + 256 * i] = src[tid + 256 * i];
    }
    if (tid < ND * NH / 4) {
        ((ulonglong2*)sW1)[tid] = ((const ulonglong2*)(W1 + (size_t)a * ND * NH))[tid];
    }
    if (tid < NH / 4) {
        ((ulonglong2*)sW3)[tid] = ((const ulonglong2*)(W3 + (size_t)a * NH))[tid];
        ((ulonglong2*)sB1)[tid] = ((const ulonglong2*)(b1 + (size_t)a * NH))[tid];
        ((ulonglong2*)sB2)[tid] = ((const ulonglong2*)(b2 + (size_t)a * NH))[tid];
    }
    if (tid == 0) sB3 = b3[a];
    __syncthreads();

    // ---- one struct per thread ----
    const int s = blockIdx.y * 256 + tid;               // NS % 256 == 0
    const float* gp = g + ((size_t)s * NA + a) * ND;
    u64 g2[ND];
    #pragma unroll
    for (int d = 0; d < ND; d++) g2[d] = dup2(gp[d]);

    // ---- layer 1: [5] -> [64], tanh (packed over neuron pairs) ----
    float h1[NH];
    #pragma unroll
    for (int j2 = 0; j2 < NH / 2; j2++) {
        u64 acc = sB1[j2];
        #pragma unroll
        for (int d = 0; d < ND; d++)
            acc = fma2(g2[d], sW1[d * (NH / 2) + j2], acc);
        float lo, hi; unpack2(acc, lo, hi);
        h1[2 * j2 + 0] = fast_tanh(lo);
        h1[2 * j2 + 1] = fast_tanh(hi);
    }

    // ---- layer 2: [64] -> [64], k-outer, all 32 pair-accumulators in regs ----
    u64 acc[NH / 2];
    #pragma unroll
    for (int j2 = 0; j2 < NH / 2; j2++) acc[j2] = sB2[j2];

    #pragma unroll 4
    for (int k = 0; k < NH; k++) {
        const u64 hk2 = dup2(h1[k]);
        const u64* w  = &sW2[k * (NH / 2)];
        #pragma unroll
        for (int j2 = 0; j2 < NH / 2; j2++)
            acc[j2] = fma2(hk2, w[j2], acc[j2]);
    }

    // ---- tanh + layer 3 dot ----
    u64 e2 = 0ull;                                      // (0.0f, 0.0f)
    #pragma unroll
    for (int j2 = 0; j2 < NH / 2; j2++) {
        float lo, hi; unpack2(acc[j2], lo, hi);
        u64 t2 = pack2(fast_tanh(lo), fast_tanh(hi));
        e2 = fma2(t2, sW3[j2], e2);
    }
    float elo, ehi; unpack2(e2, elo, ehi);
    out[(size_t)s * NA + a] = elo + ehi + sB3;
}

extern "C" void kernel_launch(void* const* d_in, const int* in_sizes, int n_in,
                              void* d_out, int out_size) {
    const float* g  = (const float*)d_in[0];
    const float* W1 = (const float*)d_in[1];
    const float* b1 = (const float*)d_in[2];
    const float* W2 = (const float*)d_in[3];
    const float* b2 = (const float*)d_in[4];
    const float* W3 = (const float*)d_in[5];
    const float* b3 = (const float*)d_in[6];
    float* out = (float*)d_out;

    dim3 grid(NA, NS / 256);
    mlp_grouped_kernel<<<grid, 256>>>(g, W1, b1, W2, b2, W3, b3, out);
}

// round 3
// speedup vs baseline: 1.1783x; 1.1783x over previous
#include <cuda_runtime.h>

#define NS 4096
#define NA 1024
#define ND 5
#define NH 64

typedef unsigned long long u64;

// ---- packed f32x2 helpers (sm_103a FFMA2, reachable only via PTX) ----
__device__ __forceinline__ u64 pack2(float lo, float hi) {
    u64 r; asm("mov.b64 %0, {%1, %2};" : "=l"(r) : "f"(lo), "f"(hi)); return r;
}
__device__ __forceinline__ u64 dup2(float x) {
    u64 r; asm("mov.b64 %0, {%1, %1};" : "=l"(r) : "f"(x)); return r;
}
__device__ __forceinline__ void unpack2(u64 v, float& lo, float& hi) {
    asm("mov.b64 {%0, %1}, %2;" : "=f"(lo), "=f"(hi) : "l"(v));
}
__device__ __forceinline__ u64 fma2(u64 a, u64 b, u64 c) {
    u64 d; asm("fma.rn.f32x2 %0, %1, %2, %3;" : "=l"(d) : "l"(a), "l"(b), "l"(c)); return d;
}

// tanh(x) = 1 - 2/(exp(2x)+1): 2 MUFU + ~3 fma-pipe ops, abs err ~1e-7.
__device__ __forceinline__ float fast_tanh(float x) {
    return 1.0f - __fdividef(2.0f, __expf(2.0f * x) + 1.0f);
}

__global__ void __launch_bounds__(256, 2) mlp_grouped_kernel(
    const float* __restrict__ g,
    const float* __restrict__ W1, const float* __restrict__ b1,
    const float* __restrict__ W2, const float* __restrict__ b2,
    const float* __restrict__ W3, const float* __restrict__ b3,
    float* __restrict__ out)
{
    // Weights as f32x2 pairs over adjacent output neurons (row-major j).
    __shared__ u64 sW1[ND * NH / 2];   // 160 pairs
    __shared__ u64 sW2[NH * NH / 2];   // 2048 pairs = 16 KB
    __shared__ u64 sW3[NH / 2];
    __shared__ u64 sB1[NH / 2];
    __shared__ u64 sB2[NH / 2];
    __shared__ float sB3v;
    // h1 staging: sh[k*256 + tid] (conflict-free; keeps k-loop rolled, regs low)
    extern __shared__ float sh[];      // 64 * 256 floats = 64 KB

    const int a   = blockIdx.x;
    const int tid = threadIdx.x;

    // ---- stage this atom's weights (contiguous 16B copies) ----
    {
        const ulonglong2* src = (const ulonglong2*)(W2 + (size_t)a * NH * NH);
        ulonglong2* dst = (ulonglong2*)sW2;
        #pragma unroll
        for (int i = 0; i < 4; i++) dst[tid + 256 * i] = src[tid + 256 * i];
    }
    if (tid < ND * NH / 4)
        ((ulonglong2*)sW1)[tid] = ((const ulonglong2*)(W1 + (size_t)a * ND * NH))[tid];
    if (tid < NH / 4) {
        ((ulonglong2*)sW3)[tid] = ((const ulonglong2*)(W3 + (size_t)a * NH))[tid];
        ((ulonglong2*)sB1)[tid] = ((const ulonglong2*)(b1 + (size_t)a * NH))[tid];
        ((ulonglong2*)sB2)[tid] = ((const ulonglong2*)(b2 + (size_t)a * NH))[tid];
    }
    if (tid == 0) sB3v = b3[a];
    __syncthreads();

    // ---- one struct per thread ----
    const int s = blockIdx.y * 256 + tid;               // NS % 256 == 0
    const float* gp = g + ((size_t)s * NA + a) * ND;
    u64 g2[ND];
    #pragma unroll
    for (int d = 0; d < ND; d++) g2[d] = dup2(gp[d]);

    // ---- layer 1: [5] -> [64], tanh; result staged to smem ----
    #pragma unroll
    for (int j2 = 0; j2 < NH / 2; j2++) {
        u64 acc = sB1[j2];
        #pragma unroll
        for (int d = 0; d < ND; d++)
            acc = fma2(g2[d], sW1[d * (NH / 2) + j2], acc);
        float lo, hi; unpack2(acc, lo, hi);
        sh[(2 * j2 + 0) * 256 + tid] = fast_tanh(lo);
        sh[(2 * j2 + 1) * 256 + tid] = fast_tanh(hi);
    }
    // (no barrier: each thread reads back only its own values; program order suffices)

    // ---- layer 2 ([64]->[64], tanh) + layer 3 dot, j chunked 2 x 32 neurons ----
    u64 e2 = pack2(0.0f, 0.0f);
    #pragma unroll 1
    for (int c = 0; c < 2; c++) {
        u64 acc[16];                                    // 32 neurons as 16 pairs
        #pragma unroll
        for (int i = 0; i < 16; i++) acc[i] = sB2[c * 16 + i];

        #pragma unroll 4
        for (int k = 0; k < NH; k++) {
            const u64 hk2 = dup2(sh[k * 256 + tid]);
            const ulonglong2* w = (const ulonglong2*)&sW2[k * (NH / 2) + c * 16];
            #pragma unroll
            for (int i = 0; i < 8; i++) {               // 8 x LDS.128 -> 16 FFMA2
                ulonglong2 wv = w[i];
                acc[2 * i + 0] = fma2(hk2, wv.x, acc[2 * i + 0]);
                acc[2 * i + 1] = fma2(hk2, wv.y, acc[2 * i + 1]);
            }
        }
        #pragma unroll
        for (int i = 0; i < 16; i++) {
            float lo, hi; unpack2(acc[i], lo, hi);
            u64 t2 = pack2(fast_tanh(lo), fast_tanh(hi));
            e2 = fma2(t2, sW3[c * 16 + i], e2);
        }
    }
    float elo, ehi; unpack2(e2, elo, ehi);
    out[(size_t)s * NA + a] = elo + ehi + sB3v;
}

extern "C" void kernel_launch(void* const* d_in, const int* in_sizes, int n_in,
                              void* d_out, int out_size) {
    const float* g  = (const float*)d_in[0];
    const float* W1 = (const float*)d_in[1];
    const float* b1 = (const float*)d_in[2];
    const float* W2 = (const float*)d_in[3];
    const float* b2 = (const float*)d_in[4];
    const float* W3 = (const float*)d_in[5];
    const float* b3 = (const float*)d_in[6];
    float* out = (float*)d_out;

    const int dyn_smem = 64 * 256 * (int)sizeof(float);   // 64 KB h1 staging
    cudaFuncSetAttribute(mlp_grouped_kernel,
                         cudaFuncAttributeMaxDynamicSharedMemorySize, dyn_smem);

    dim3 grid(NA, NS / 256);
    mlp_grouped_kernel<<<grid, 256, dyn_smem>>>(g, W1, b1, W2, b2, W3, b3, out);
}

// round 6
// speedup vs baseline: 1.8823x; 1.5975x over previous
#include <cuda_runtime.h>
#include <cuda_fp16.h>
#include <cstdint>

#define NS 4096
#define NA 1024
#define ND 5
#define NH 64
#define TILES 4
#define PADK 72          // f16 elems per row (144B): ldmatrix bank-conflict-free

struct Smem {
    __half w2hi[NH][PADK];     // B^T: [j_out][k_in], hi part
    __half w2lo[NH][PADK];
    __half hhi[128][PADK];     // activations, hi part
    __half hlo[128][PADK];
    float  w1[ND][NH];
    float  b1[NH], b2[NH], w3[NH];
};

__device__ __forceinline__ uint32_t smem_u32(const void* p) {
    uint32_t a;
    asm("{ .reg .u64 t; cvta.to.shared.u64 t, %1; cvt.u32.u64 %0, t; }" : "=r"(a) : "l"(p));
    return a;
}
__device__ __forceinline__ void ldsm_x4(uint32_t r[4], uint32_t addr) {
    asm volatile("ldmatrix.sync.aligned.m8n8.x4.shared.b16 {%0,%1,%2,%3}, [%4];"
                 : "=r"(r[0]), "=r"(r[1]), "=r"(r[2]), "=r"(r[3]) : "r"(addr));
}
__device__ __forceinline__ void ldsm_x2(uint32_t r[2], uint32_t addr) {
    asm volatile("ldmatrix.sync.aligned.m8n8.x2.shared.b16 {%0,%1}, [%2];"
                 : "=r"(r[0]), "=r"(r[1]) : "r"(addr));
}
__device__ __forceinline__ void mma16816(float c[4], const uint32_t a[4], const uint32_t b[2]) {
    asm volatile("mma.sync.aligned.m16n8k16.row.col.f32.f16.f16.f32 "
                 "{%0,%1,%2,%3}, {%4,%5,%6,%7}, {%8,%9}, {%0,%1,%2,%3};"
                 : "+f"(c[0]), "+f"(c[1]), "+f"(c[2]), "+f"(c[3])
                 : "r"(a[0]), "r"(a[1]), "r"(a[2]), "r"(a[3]), "r"(b[0]), "r"(b[1]));
}

// tanh(x) = 1 - 2/(exp(2x)+1): 2 MUFU + ~3 fma, abs err ~1e-7
__device__ __forceinline__ float fast_tanh(float x) {
    return 1.0f - __fdividef(2.0f, __expf(2.0f * x) + 1.0f);
}
__device__ __forceinline__ uint32_t h2u(__half2 h) { return *reinterpret_cast<uint32_t*>(&h); }

__global__ void __launch_bounds__(128) mlp_hmma_kernel(
    const float* __restrict__ g,
    const float* __restrict__ W1, const float* __restrict__ b1,
    const float* __restrict__ W2, const float* __restrict__ b2,
    const float* __restrict__ W3, const float* __restrict__ b3,
    float* __restrict__ out)
{
    extern __shared__ __align__(16) char smem_raw[];
    Smem* sm = reinterpret_cast<Smem*>(smem_raw);

    const int a    = blockIdx.x;
    const int tid  = threadIdx.x;
    const int w    = tid >> 5;
    const int lane = tid & 31;

    // ---- stage weights: W2 -> transposed split-f16 tiles; W1/biases fp32 ----
    for (int e = tid; e < NH * NH; e += 128) {
        int kin = e >> 6, j = e & 63;                    // W2[a][kin][j]
        float v = W2[(size_t)a * NH * NH + e];
        __half hi = __float2half_rn(v);
        sm->w2hi[j][kin] = hi;
        sm->w2lo[j][kin] = __float2half_rn(v - __half2float(hi));
    }
    for (int e = tid; e < ND * NH; e += 128)
        (&sm->w1[0][0])[e] = W1[(size_t)a * ND * NH + e];
    if (tid < NH) {
        sm->b1[tid] = b1[(size_t)a * NH + tid];
        sm->b2[tid] = b2[(size_t)a * NH + tid];
        sm->w3[tid] = W3[(size_t)a * NH + tid];
    }
    __syncthreads();

    const float bias3 = b3[a];

    // lane-specific ldmatrix base addresses
    const uint32_t aAhi = smem_u32(&sm->hhi[w * 32 + (lane & 15)][0]) + (lane >> 4) * 16;
    const uint32_t aAlo = smem_u32(&sm->hlo[w * 32 + (lane & 15)][0]) + (lane >> 4) * 16;
    const uint32_t aBhi = smem_u32(&sm->w2hi[lane & 7][0]) + ((lane >> 3) & 1) * 16;
    const uint32_t aBlo = smem_u32(&sm->w2lo[lane & 7][0]) + ((lane >> 3) & 1) * 16;

#pragma unroll 1
    for (int t = 0; t < TILES; t++) {
        const int sb = (blockIdx.y * TILES + t) * 128;   // struct base of this tile
        const int s  = sb + tid;

        __syncwarp();   // prior tile's ldmatrix reads done before rewriting h rows

        // ---- layer 1 (fp32 scalar): h = tanh(g*W1 + b1), split hi/lo -> smem ----
        {
            const float* gp = g + ((size_t)s * NA + a) * ND;
            float gv[ND];
#pragma unroll
            for (int d = 0; d < ND; d++) gv[d] = gp[d];

            float h[NH];
            const float4* w1v = (const float4*)&sm->w1[0][0];
            const float4* b1v = (const float4*)sm->b1;
#pragma unroll
            for (int j4 = 0; j4 < NH / 4; j4++) {
                float4 acc = b1v[j4];
#pragma unroll
                for (int d = 0; d < ND; d++) {
                    float4 wv = w1v[d * (NH / 4) + j4];
                    acc.x = fmaf(gv[d], wv.x, acc.x);
                    acc.y = fmaf(gv[d], wv.y, acc.y);
                    acc.z = fmaf(gv[d], wv.z, acc.z);
                    acc.w = fmaf(gv[d], wv.w, acc.w);
                }
                h[4 * j4 + 0] = fast_tanh(acc.x);
                h[4 * j4 + 1] = fast_tanh(acc.y);
                h[4 * j4 + 2] = fast_tanh(acc.z);
                h[4 * j4 + 3] = fast_tanh(acc.w);
            }
#pragma unroll
            for (int c = 0; c < 8; c++) {                // 8 cols per 16B chunk
                uint32_t hi[4], lo[4];
#pragma unroll
                for (int q = 0; q < 4; q++) {
                    float x = h[8 * c + 2 * q], y = h[8 * c + 2 * q + 1];
                    __half2 h2 = __floats2half2_rn(x, y);
                    float2  hf = __half22float2(h2);
                    hi[q] = h2u(h2);
                    lo[q] = h2u(__floats2half2_rn(x - hf.x, y - hf.y));
                }
                *(uint4*)&sm->hhi[tid][8 * c] = make_uint4(hi[0], hi[1], hi[2], hi[3]);
                *(uint4*)&sm->hlo[tid][8 * c] = make_uint4(lo[0], lo[1], lo[2], lo[3]);
            }
        }
        __syncwarp();

        // ---- layer 2: 32x64x64 split-f16 HMMA, bias folded into acc init ----
        float acc[2][8][4];
#pragma unroll
        for (int nt = 0; nt < 8; nt++) {
            float2 b2v = *(const float2*)&sm->b2[nt * 8 + (lane & 3) * 2];
#pragma unroll
            for (int mt = 0; mt < 2; mt++) {
                acc[mt][nt][0] = b2v.x; acc[mt][nt][1] = b2v.y;
                acc[mt][nt][2] = b2v.x; acc[mt][nt][3] = b2v.y;
            }
        }
#pragma unroll
        for (int ks = 0; ks < 4; ks++) {
            uint32_t bh[8][2], bl[8][2], ah[2][4], al[2][4];
#pragma unroll
            for (int nt = 0; nt < 8; nt++) {
                ldsm_x2(bh[nt], aBhi + nt * 8 * (PADK * 2) + ks * 32);
                ldsm_x2(bl[nt], aBlo + nt * 8 * (PADK * 2) + ks * 32);
            }
#pragma unroll
            for (int mt = 0; mt < 2; mt++) {
                ldsm_x4(ah[mt], aAhi + mt * 16 * (PADK * 2) + ks * 32);
                ldsm_x4(al[mt], aAlo + mt * 16 * (PADK * 2) + ks * 32);
            }
#pragma unroll
            for (int mt = 0; mt < 2; mt++)
#pragma unroll
                for (int nt = 0; nt < 8; nt++) {
                    mma16816(acc[mt][nt], ah[mt], bh[nt]);
                    mma16816(acc[mt][nt], al[mt], bh[nt]);
                    mma16816(acc[mt][nt], ah[mt], bl[nt]);
                }
        }

        // ---- epilogue: tanh + dot(W3), quad-shuffle reduce, write 4 rows ----
        float p0 = 0.f, p1 = 0.f, p2 = 0.f, p3 = 0.f;
#pragma unroll
        for (int nt = 0; nt < 8; nt++) {
            float2 w3v = *(const float2*)&sm->w3[nt * 8 + (lane & 3) * 2];
            p0 = fmaf(fast_tanh(acc[0][nt][0]), w3v.x, p0);
            p0 = fmaf(fast_tanh(acc[0][nt][1]), w3v.y, p0);
            p1 = fmaf(fast_tanh(acc[0][nt][2]), w3v.x, p1);
            p1 = fmaf(fast_tanh(acc[0][nt][3]), w3v.y, p1);
            p2 = fmaf(fast_tanh(acc[1][nt][0]), w3v.x, p2);
            p2 = fmaf(fast_tanh(acc[1][nt][1]), w3v.y, p2);
            p3 = fmaf(fast_tanh(acc[1][nt][2]), w3v.x, p3);
            p3 = fmaf(fast_tanh(acc[1][nt][3]), w3v.y, p3);
        }
#pragma unroll
        for (int d = 1; d <= 2; d <<= 1) {
            p0 += __shfl_xor_sync(0xFFFFFFFFu, p0, d);
            p1 += __shfl_xor_sync(0xFFFFFFFFu, p1, d);
            p2 += __shfl_xor_sync(0xFFFFFFFFu, p2, d);
            p3 += __shfl_xor_sync(0xFFFFFFFFu, p3, d);
        }
        if ((lane & 3) == 0) {
            const int q  = lane >> 2;
            const int rb = sb + w * 32 + q;
            out[(size_t)(rb +  0) * NA + a] = p0 + bias3;
            out[(size_t)(rb +  8) * NA + a] = p1 + bias3;
            out[(size_t)(rb + 16) * NA + a] = p2 + bias3;
            out[(size_t)(rb + 24) * NA + a] = p3 + bias3;
        }
    }
}

extern "C" void kernel_launch(void* const* d_in, const int* in_sizes, int n_in,
                              void* d_out, int out_size) {
    const float* g  = (const float*)d_in[0];
    const float* W1 = (const float*)d_in[1];
    const float* b1 = (const float*)d_in[2];
    const float* W2 = (const float*)d_in[3];
    const float* b2 = (const float*)d_in[4];
    const float* W3 = (const float*)d_in[5];
    const float* b3 = (const float*)d_in[6];
    float* out = (float*)d_out;

    const int dyn = (int)sizeof(Smem);
    cudaFuncSetAttribute(mlp_hmma_kernel,
                         cudaFuncAttributeMaxDynamicSharedMemorySize, dyn);

    dim3 grid(NA, NS / (128 * TILES));   // 1024 x 8
    mlp_hmma_kernel<<<grid, 128, dyn>>>(g, W1, b1, W2, b2, W3, b3, out);
}

// round 8
// speedup vs baseline: 3.4691x; 1.8430x over previous
#include <cuda_runtime.h>
#include <cuda_fp16.h>
#include <cstdint>

#define NS 4096
#define NA 1024
#define ND 5
#define NH 64
#define TILES 4
#define PADK 72          // f16 elems per row (144B): ldmatrix bank-conflict-free

struct Smem {
    __half w2hi[NH][PADK];     // B^T: [j_out][k_in], hi part
    __half w2lo[NH][PADK];
    __half hhi[128][PADK];     // activations, hi part
    __half hlo[128][PADK];
    float  w1[ND][NH];
    float  b1[NH], b2[NH], w3[NH];
};

__device__ __forceinline__ uint32_t smem_u32(const void* p) {
    uint32_t a;
    asm("{ .reg .u64 t; cvta.to.shared.u64 t, %1; cvt.u32.u64 %0, t; }" : "=r"(a) : "l"(p));
    return a;
}
__device__ __forceinline__ void ldsm_x4(uint32_t r[4], uint32_t addr) {
    asm volatile("ldmatrix.sync.aligned.m8n8.x4.shared.b16 {%0,%1,%2,%3}, [%4];"
                 : "=r"(r[0]), "=r"(r[1]), "=r"(r[2]), "=r"(r[3]) : "r"(addr));
}
__device__ __forceinline__ void ldsm_x2(uint32_t r[2], uint32_t addr) {
    asm volatile("ldmatrix.sync.aligned.m8n8.x2.shared.b16 {%0,%1}, [%2];"
                 : "=r"(r[0]), "=r"(r[1]) : "r"(addr));
}
__device__ __forceinline__ void mma16816(float c[4], const uint32_t a[4], const uint32_t b[2]) {
    asm volatile("mma.sync.aligned.m16n8k16.row.col.f32.f16.f16.f32 "
                 "{%0,%1,%2,%3}, {%4,%5,%6,%7}, {%8,%9}, {%0,%1,%2,%3};"
                 : "+f"(c[0]), "+f"(c[1]), "+f"(c[2]), "+f"(c[3])
                 : "r"(a[0]), "r"(a[1]), "r"(a[2]), "r"(a[3]), "r"(b[0]), "r"(b[1]));
}

// HW tanh: single MUFU.TANH op (PTX tanh.approx.f32, baseline sm_75+).
// Max abs err ~2^-11; error vanishes in the saturated region.
__device__ __forceinline__ float fast_tanh(float x) {
    float y;
    asm("tanh.approx.f32 %0, %1;" : "=f"(y) : "f"(x));
    return y;
}
__device__ __forceinline__ uint32_t h2u(__half2 h) { return *reinterpret_cast<uint32_t*>(&h); }

__global__ void __launch_bounds__(128) mlp_hmma_kernel(
    const float* __restrict__ g,
    const float* __restrict__ W1, const float* __restrict__ b1,
    const float* __restrict__ W2, const float* __restrict__ b2,
    const float* __restrict__ W3, const float* __restrict__ b3,
    float* __restrict__ out)
{
    extern __shared__ __align__(16) char smem_raw[];
    Smem* sm = reinterpret_cast<Smem*>(smem_raw);

    const int a    = blockIdx.x;
    const int tid  = threadIdx.x;
    const int w    = tid >> 5;
    const int lane = tid & 31;

    // ---- stage weights: W2 -> transposed split-f16 tiles; W1/biases fp32 ----
    for (int e = tid; e < NH * NH; e += 128) {
        int kin = e >> 6, j = e & 63;                    // W2[a][kin][j]
        float v = W2[(size_t)a * NH * NH + e];
        __half hi = __float2half_rn(v);
        sm->w2hi[j][kin] = hi;
        sm->w2lo[j][kin] = __float2half_rn(v - __half2float(hi));
    }
    for (int e = tid; e < ND * NH; e += 128)
        (&sm->w1[0][0])[e] = W1[(size_t)a * ND * NH + e];
    if (tid < NH) {
        sm->b1[tid] = b1[(size_t)a * NH + tid];
        sm->b2[tid] = b2[(size_t)a * NH + tid];
        sm->w3[tid] = W3[(size_t)a * NH + tid];
    }
    __syncthreads();

    const float bias3 = b3[a];

    // lane-specific ldmatrix base addresses
    const uint32_t aAhi = smem_u32(&sm->hhi[w * 32 + (lane & 15)][0]) + (lane >> 4) * 16;
    const uint32_t aAlo = smem_u32(&sm->hlo[w * 32 + (lane & 15)][0]) + (lane >> 4) * 16;
    const uint32_t aBhi = smem_u32(&sm->w2hi[lane & 7][0]) + ((lane >> 3) & 1) * 16;
    const uint32_t aBlo = smem_u32(&sm->w2lo[lane & 7][0]) + ((lane >> 3) & 1) * 16;

#pragma unroll 1
    for (int t = 0; t < TILES; t++) {
        const int sb = (blockIdx.y * TILES + t) * 128;   // struct base of this tile
        const int s  = sb + tid;

        __syncwarp();   // prior tile's ldmatrix reads done before rewriting h rows

        // ---- layer 1 (fp32 scalar): h = tanh(g*W1 + b1), split hi/lo -> smem ----
        {
            const float* gp = g + ((size_t)s * NA + a) * ND;
            float gv[ND];
#pragma unroll
            for (int d = 0; d < ND; d++) gv[d] = gp[d];

            float h[NH];
            const float4* w1v = (const float4*)&sm->w1[0][0];
            const float4* b1v = (const float4*)sm->b1;
#pragma unroll
            for (int j4 = 0; j4 < NH / 4; j4++) {
                float4 acc = b1v[j4];
#pragma unroll
                for (int d = 0; d < ND; d++) {
                    float4 wv = w1v[d * (NH / 4) + j4];
                    acc.x = fmaf(gv[d], wv.x, acc.x);
                    acc.y = fmaf(gv[d], wv.y, acc.y);
                    acc.z = fmaf(gv[d], wv.z, acc.z);
                    acc.w = fmaf(gv[d], wv.w, acc.w);
                }
                h[4 * j4 + 0] = fast_tanh(acc.x);
                h[4 * j4 + 1] = fast_tanh(acc.y);
                h[4 * j4 + 2] = fast_tanh(acc.z);
                h[4 * j4 + 3] = fast_tanh(acc.w);
            }
#pragma unroll
            for (int c = 0; c < 8; c++) {                // 8 cols per 16B chunk
                uint32_t hi[4], lo[4];
#pragma unroll
                for (int q = 0; q < 4; q++) {
                    float x = h[8 * c + 2 * q], y = h[8 * c + 2 * q + 1];
                    __half2 h2 = __floats2half2_rn(x, y);
                    float2  hf = __half22float2(h2);
                    hi[q] = h2u(h2);
                    lo[q] = h2u(__floats2half2_rn(x - hf.x, y - hf.y));
                }
                *(uint4*)&sm->hhi[tid][8 * c] = make_uint4(hi[0], hi[1], hi[2], hi[3]);
                *(uint4*)&sm->hlo[tid][8 * c] = make_uint4(lo[0], lo[1], lo[2], lo[3]);
            }
        }
        __syncwarp();

        // ---- layer 2: 32x64x64 split-f16 HMMA, bias folded into acc init ----
        float acc[2][8][4];
#pragma unroll
        for (int nt = 0; nt < 8; nt++) {
            float2 b2v = *(const float2*)&sm->b2[nt * 8 + (lane & 3) * 2];
#pragma unroll
            for (int mt = 0; mt < 2; mt++) {
                acc[mt][nt][0] = b2v.x; acc[mt][nt][1] = b2v.y;
                acc[mt][nt][2] = b2v.x; acc[mt][nt][3] = b2v.y;
            }
        }
#pragma unroll
        for (int ks = 0; ks < 4; ks++) {
            uint32_t bh[8][2], bl[8][2], ah[2][4], al[2][4];
#pragma unroll
            for (int nt = 0; nt < 8; nt++) {
                ldsm_x2(bh[nt], aBhi + nt * 8 * (PADK * 2) + ks * 32);
                ldsm_x2(bl[nt], aBlo + nt * 8 * (PADK * 2) + ks * 32);
            }
#pragma unroll
            for (int mt = 0; mt < 2; mt++) {
                ldsm_x4(ah[mt], aAhi + mt * 16 * (PADK * 2) + ks * 32);
                ldsm_x4(al[mt], aAlo + mt * 16 * (PADK * 2) + ks * 32);
            }
#pragma unroll
            for (int mt = 0; mt < 2; mt++)
#pragma unroll
                for (int nt = 0; nt < 8; nt++) {
                    mma16816(acc[mt][nt], ah[mt], bh[nt]);
                    mma16816(acc[mt][nt], al[mt], bh[nt]);
                    mma16816(acc[mt][nt], ah[mt], bl[nt]);
                }
        }

        // ---- epilogue: tanh + dot(W3), quad-shuffle reduce, write 4 rows ----
        float p0 = 0.f, p1 = 0.f, p2 = 0.f, p3 = 0.f;
#pragma unroll
        for (int nt = 0; nt < 8; nt++) {
            float2 w3v = *(const float2*)&sm->w3[nt * 8 + (lane & 3) * 2];
            p0 = fmaf(fast_tanh(acc[0][nt][0]), w3v.x, p0);
            p0 = fmaf(fast_tanh(acc[0][nt][1]), w3v.y, p0);
            p1 = fmaf(fast_tanh(acc[0][nt][2]), w3v.x, p1);
            p1 = fmaf(fast_tanh(acc[0][nt][3]), w3v.y, p1);
            p2 = fmaf(fast_tanh(acc[1][nt][0]), w3v.x, p2);
            p2 = fmaf(fast_tanh(acc[1][nt][1]), w3v.y, p2);
            p3 = fmaf(fast_tanh(acc[1][nt][2]), w3v.x, p3);
            p3 = fmaf(fast_tanh(acc[1][nt][3]), w3v.y, p3);
        }
#pragma unroll
        for (int d = 1; d <= 2; d <<= 1) {
            p0 += __shfl_xor_sync(0xFFFFFFFFu, p0, d);
            p1 += __shfl_xor_sync(0xFFFFFFFFu, p1, d);
            p2 += __shfl_xor_sync(0xFFFFFFFFu, p2, d);
            p3 += __shfl_xor_sync(0xFFFFFFFFu, p3, d);
        }
        if ((lane & 3) == 0) {
            const int q  = lane >> 2;
            const int rb = sb + w * 32 + q;
            out[(size_t)(rb +  0) * NA + a] = p0 + bias3;
            out[(size_t)(rb +  8) * NA + a] = p1 + bias3;
            out[(size_t)(rb + 16) * NA + a] = p2 + bias3;
            out[(size_t)(rb + 24) * NA + a] = p3 + bias3;
        }
    }
}

extern "C" void kernel_launch(void* const* d_in, const int* in_sizes, int n_in,
                              void* d_out, int out_size) {
    const float* g  = (const float*)d_in[0];
    const float* W1 = (const float*)d_in[1];
    const float* b1 = (const float*)d_in[2];
    const float* W2 = (const float*)d_in[3];
    const float* b2 = (const float*)d_in[4];
    const float* W3 = (const float*)d_in[5];
    const float* b3 = (const float*)d_in[6];
    float* out = (float*)d_out;

    const int dyn = (int)sizeof(Smem);
    cudaFuncSetAttribute(mlp_hmma_kernel,
                         cudaFuncAttributeMaxDynamicSharedMemorySize, dyn);

    dim3 grid(NA, NS / (128 * TILES));   // 1024 x 8
    mlp_hmma_kernel<<<grid, 128, dyn>>>(g, W1, b1, W2, b2, W3, b3, out);
}

// round 9
// speedup vs baseline: 4.1388x; 1.1930x over previous
#include <cuda_runtime.h>
#include <cuda_fp16.h>
#include <cstdint>

#define NS 4096
#define NA 1024
#define ND 5
#define NH 64
#define TILES 4
#define PADK 72          // f16 elems per row (144B): ldmatrix bank-conflict-free

struct Smem {
    __half   w2hi[NH][PADK];     // B^T: [j_out][k_in], f16 hi
    __half   w2lo[NH][PADK];     // f16 residual
    uint32_t w1ph[4][72];        // W1ext pairs (k,k+1) as f16x2: [kpair][j], padded
    uint32_t w1pl[4][72];
    float    b2[NH], w3[NH];
};

__device__ __forceinline__ uint32_t smem_u32(const void* p) {
    uint32_t a;
    asm("{ .reg .u64 t; cvta.to.shared.u64 t, %1; cvt.u32.u64 %0, t; }" : "=r"(a) : "l"(p));
    return a;
}
__device__ __forceinline__ void ldsm_x2(uint32_t r[2], uint32_t addr) {
    asm volatile("ldmatrix.sync.aligned.m8n8.x2.shared.b16 {%0,%1}, [%2];"
                 : "=r"(r[0]), "=r"(r[1]) : "r"(addr));
}
__device__ __forceinline__ void mma16816(float c[4], const uint32_t a[4], const uint32_t b[2]) {
    asm volatile("mma.sync.aligned.m16n8k16.row.col.f32.f16.f16.f32 "
                 "{%0,%1,%2,%3}, {%4,%5,%6,%7}, {%8,%9}, {%0,%1,%2,%3};"
                 : "+f"(c[0]), "+f"(c[1]), "+f"(c[2]), "+f"(c[3])
                 : "r"(a[0]), "r"(a[1]), "r"(a[2]), "r"(a[3]), "r"(b[0]), "r"(b[1]));
}
__device__ __forceinline__ void mma16816_z(float c[4], const uint32_t a[4], const uint32_t b[2]) {
    asm volatile("mma.sync.aligned.m16n8k16.row.col.f32.f16.f16.f32 "
                 "{%0,%1,%2,%3}, {%4,%5,%6,%7}, {%8,%9}, {%10,%10,%10,%10};"
                 : "=f"(c[0]), "=f"(c[1]), "=f"(c[2]), "=f"(c[3])
                 : "r"(a[0]), "r"(a[1]), "r"(a[2]), "r"(a[3]), "r"(b[0]), "r"(b[1]),
                   "f"(0.0f));
}
__device__ __forceinline__ void mma16808(float c[4], uint32_t a0, uint32_t a1, uint32_t b0) {
    asm volatile("mma.sync.aligned.m16n8k8.row.col.f32.f16.f16.f32 "
                 "{%0,%1,%2,%3}, {%4,%5}, {%6}, {%0,%1,%2,%3};"
                 : "+f"(c[0]), "+f"(c[1]), "+f"(c[2]), "+f"(c[3])
                 : "r"(a0), "r"(a1), "r"(b0));
}
__device__ __forceinline__ void mma16808_z(float c[4], uint32_t a0, uint32_t a1, uint32_t b0) {
    asm volatile("mma.sync.aligned.m16n8k8.row.col.f32.f16.f16.f32 "
                 "{%0,%1,%2,%3}, {%4,%5}, {%6}, {%7,%7,%7,%7};"
                 : "=f"(c[0]), "=f"(c[1]), "=f"(c[2]), "=f"(c[3])
                 : "r"(a0), "r"(a1), "r"(b0), "f"(0.0f));
}

// HW tanh: single MUFU.TANH (PTX tanh.approx.f32, baseline sm_75+).
__device__ __forceinline__ float fast_tanh(float x) {
    float y;
    asm("tanh.approx.f32 %0, %1;" : "=f"(y) : "f"(x));
    return y;
}
__device__ __forceinline__ uint32_t h2u(__half2 h) { return *reinterpret_cast<uint32_t*>(&h); }

// split (x,y) into f16x2 hi + f16x2 residual
__device__ __forceinline__ void split2(float x, float y, uint32_t& hi, uint32_t& lo) {
    __half2 h = __floats2half2_rn(x, y);
    float2  f = __half22float2(h);
    hi = h2u(h);
    lo = h2u(__floats2half2_rn(x - f.x, y - f.y));
}

__global__ void __launch_bounds__(128, 3) mlp_hmma2_kernel(
    const float* __restrict__ g,
    const float* __restrict__ W1, const float* __restrict__ b1,
    const float* __restrict__ W2, const float* __restrict__ b2,
    const float* __restrict__ W3, const float* __restrict__ b3,
    float* __restrict__ out)
{
    extern __shared__ __align__(16) char smem_raw[];
    Smem* sm = reinterpret_cast<Smem*>(smem_raw);

    const int a    = blockIdx.x;
    const int tid  = threadIdx.x;
    const int w    = tid >> 5;
    const int lane = tid & 31;
    const int q    = lane & 3;
    const int r0   = lane >> 2;

    // ---- stage W2 -> transposed split-f16 tiles (proven round-6 layout) ----
    for (int e = tid; e < NH * NH; e += 128) {
        int kin = e >> 6, j = e & 63;                    // W2[a][kin][j]
        float v = W2[(size_t)a * NH * NH + e];
        __half hi = __float2half_rn(v);
        sm->w2hi[j][kin] = hi;
        sm->w2lo[j][kin] = __float2half_rn(v - __half2float(hi));
    }
    // ---- stage W1ext pairs: rows 0..4 = W1, row 5 = b1, rows 6,7 = 0 ----
    for (int e = tid; e < 256; e += 128) {
        int kp = e >> 6, j = e & 63;
        int k0 = 2 * kp, k1 = k0 + 1;
        float x = (k0 < ND) ? W1[(size_t)a * ND * NH + k0 * NH + j] : 0.0f;
        float y = (k1 < ND) ? W1[(size_t)a * ND * NH + k1 * NH + j]
                            : ((k1 == ND) ? b1[(size_t)a * NH + j] : 0.0f);
        uint32_t hi, lo;
        split2(x, y, hi, lo);
        sm->w1ph[kp][j] = hi;
        sm->w1pl[kp][j] = lo;
    }
    if (tid < NH) {
        sm->b2[tid] = b2[(size_t)a * NH + tid];
        sm->w3[tid] = W3[(size_t)a * NH + tid];
    }
    __syncthreads();

    const float bias3 = b3[a];
    const uint32_t aBhi = smem_u32(&sm->w2hi[lane & 7][0]) + ((lane >> 3) & 1) * 16;
    const uint32_t aBlo = smem_u32(&sm->w2lo[lane & 7][0]) + ((lane >> 3) & 1) * 16;

#pragma unroll 1
    for (int t = 0; t < TILES; t++) {
        const int swb = (blockIdx.y * TILES + t) * 128 + w * 32;  // warp's struct base

        // ---- W1ext B-fragments (m16n8k8): lane holds W1e[(q*2, q*2+1)][nt*8 + r0] ----
        uint32_t bw1h[8], bw1l[8];
#pragma unroll
        for (int nt = 0; nt < 8; nt++) {
            bw1h[nt] = sm->w1ph[q][nt * 8 + r0];
            bw1l[nt] = sm->w1pl[q][nt * 8 + r0];
        }

        // ---- g A-fragments (m16n8k8): d-pair (2q, 2q+1); d=5 slot carries 1.0 (bias) ----
        uint32_t gh[2][2], gl[2][2];
#pragma unroll
        for (int mt = 0; mt < 2; mt++)
#pragma unroll
            for (int rr = 0; rr < 2; rr++) {
                const int srow = swb + mt * 16 + r0 + 8 * rr;
                const size_t idx = ((size_t)srow * NA + a) * ND;
                const int d0 = 2 * q;
                float x = (d0 < ND)     ? g[idx + d0]     : 0.0f;
                float y = (d0 + 1 < ND) ? g[idx + d0 + 1] : ((d0 + 1 == ND) ? 1.0f : 0.0f);
                split2(x, y, gh[mt][rr], gl[mt][rr]);
            }

        // ---- layer-1 MMA: z1 = gext * W1ext (3-term split), acc init via zero-C ----
        float acc1[2][8][4];
#pragma unroll
        for (int mt = 0; mt < 2; mt++)
#pragma unroll
            for (int nt = 0; nt < 8; nt++) {
                mma16808_z(acc1[mt][nt], gh[mt][0], gh[mt][1], bw1h[nt]);
                mma16808 (acc1[mt][nt], gl[mt][0], gl[mt][1], bw1h[nt]);
                mma16808 (acc1[mt][nt], gh[mt][0], gh[mt][1], bw1l[nt]);
            }

        // ---- layer-2: tanh+split acc1 -> A-frags in-register (no smem round-trip) ----
        float acc[2][8][4];
#pragma unroll
        for (int ks = 0; ks < 4; ks++) {
            uint32_t ah[2][4], al[2][4];
#pragma unroll
            for (int mt = 0; mt < 2; mt++) {
                const float* e0 = acc1[mt][2 * ks];      // cols ks*16 + (q*2..+1)
                const float* e1 = acc1[mt][2 * ks + 1];  // cols ks*16+8 + ...
                split2(fast_tanh(e0[0]), fast_tanh(e0[1]), ah[mt][0], al[mt][0]);
                split2(fast_tanh(e0[2]), fast_tanh(e0[3]), ah[mt][1], al[mt][1]);
                split2(fast_tanh(e1[0]), fast_tanh(e1[1]), ah[mt][2], al[mt][2]);
                split2(fast_tanh(e1[2]), fast_tanh(e1[3]), ah[mt][3], al[mt][3]);
            }
#pragma unroll
            for (int nt = 0; nt < 8; nt++) {
                uint32_t bh2[2], bl2[2];
                ldsm_x2(bh2, aBhi + nt * 8 * (PADK * 2) + ks * 32);
                ldsm_x2(bl2, aBlo + nt * 8 * (PADK * 2) + ks * 32);
#pragma unroll
                for (int mt = 0; mt < 2; mt++) {
                    if (ks == 0) mma16816_z(acc[mt][nt], ah[mt], bh2);
                    else         mma16816 (acc[mt][nt], ah[mt], bh2);
                    mma16816(acc[mt][nt], al[mt], bh2);
                    mma16816(acc[mt][nt], ah[mt], bl2);
                }
            }
        }

        // ---- epilogue: +b2, tanh, dot(W3), quad-shuffle reduce, write 4 rows ----
        float p0 = 0.f, p1 = 0.f, p2 = 0.f, p3 = 0.f;
#pragma unroll
        for (int nt = 0; nt < 8; nt++) {
            float2 b2v = *(const float2*)&sm->b2[nt * 8 + q * 2];
            float2 w3v = *(const float2*)&sm->w3[nt * 8 + q * 2];
            p0 = fmaf(fast_tanh(acc[0][nt][0] + b2v.x), w3v.x, p0);
            p0 = fmaf(fast_tanh(acc[0][nt][1] + b2v.y), w3v.y, p0);
            p1 = fmaf(fast_tanh(acc[0][nt][2] + b2v.x), w3v.x, p1);
            p1 = fmaf(fast_tanh(acc[0][nt][3] + b2v.y), w3v.y, p1);
            p2 = fmaf(fast_tanh(acc[1][nt][0] + b2v.x), w3v.x, p2);
            p2 = fmaf(fast_tanh(acc[1][nt][1] + b2v.y), w3v.y, p2);
            p3 = fmaf(fast_tanh(acc[1][nt][2] + b2v.x), w3v.x, p3);
            p3 = fmaf(fast_tanh(acc[1][nt][3] + b2v.y), w3v.y, p3);
        }
#pragma unroll
        for (int d = 1; d <= 2; d <<= 1) {
            p0 += __shfl_xor_sync(0xFFFFFFFFu, p0, d);
            p1 += __shfl_xor_sync(0xFFFFFFFFu, p1, d);
            p2 += __shfl_xor_sync(0xFFFFFFFFu, p2, d);
            p3 += __shfl_xor_sync(0xFFFFFFFFu, p3, d);
        }
        if (q == 0) {
            const int rb = swb + r0;
            out[(size_t)(rb +  0) * NA + a] = p0 + bias3;
            out[(size_t)(rb +  8) * NA + a] = p1 + bias3;
            out[(size_t)(rb + 16) * NA + a] = p2 + bias3;
            out[(size_t)(rb + 24) * NA + a] = p3 + bias3;
        }
    }
}

extern "C" void kernel_launch(void* const* d_in, const int* in_sizes, int n_in,
                              void* d_out, int out_size) {
    const float* g  = (const float*)d_in[0];
    const float* W1 = (const float*)d_in[1];
    const float* b1 = (const float*)d_in[2];
    const float* W2 = (const float*)d_in[3];
    const float* b2 = (const float*)d_in[4];
    const float* W3 = (const float*)d_in[5];
    const float* b3 = (const float*)d_in[6];
    float* out = (float*)d_out;

    const int dyn = (int)sizeof(Smem);
    cudaFuncSetAttribute(mlp_hmma2_kernel,
                         cudaFuncAttributeMaxDynamicSharedMemorySize, dyn);

    dim3 grid(NA, NS / (128 * TILES));   // 1024 x 8
    mlp_hmma2_kernel<<<grid, 128, dyn>>>(g, W1, b1, W2, b2, W3, b3, out);
}